// round 1
// baseline (speedup 1.0000x reference)
#include <cuda_runtime.h>
#include <math.h>

// Problem constants (fixed by the dataset: z[16,128,32,32], e[8192,128], log_sigma[1])
#define NTOK  16384
#define MCODE 8192
#define CDIM  128
#define BDIM  16
#define HWDIM 1024

// ---- device scratch (allocation-free: module-load-time globals) ----
__device__ float g_zf[(size_t)NTOK * CDIM];   // z transposed to [N, C]
__device__ float g_zsq[NTOK];
__device__ float g_esq[MCODE];
__device__ float g_rowlse[NTOK];
__device__ float g_collse[MCODE];

// ---- packed f32x2 helpers (FFMA2 path, sm_100+) ----
__device__ __forceinline__ unsigned long long pack2(float a, float b) {
    unsigned long long r;
    asm("mov.b64 %0, {%1, %2};" : "=l"(r) : "f"(a), "f"(b));
    return r;
}
__device__ __forceinline__ void unpack2(unsigned long long v, float& a, float& b) {
    asm("mov.b64 {%0, %1}, %2;" : "=f"(a), "=f"(b) : "l"(v));
}
__device__ __forceinline__ void fma2(unsigned long long& d,
                                     unsigned long long a, unsigned long long b) {
    asm("fma.rn.f32x2 %0, %1, %2, %0;" : "+l"(d) : "l"(a), "l"(b));
}

// ---- prep: z[B,C,H,W] -> zf[N,C], n = b*HW + hw ----
__global__ void build_zf(const float* __restrict__ z, float* __restrict__ zf) {
    int i = blockIdx.x * 256 + threadIdx.x;
    if (i >= BDIM * CDIM * HWDIM) return;
    int hw = i & (HWDIM - 1);
    int bc = i >> 10;                 // HW = 1024
    int c  = bc & (CDIM - 1);
    int b  = bc >> 7;                 // C = 128
    zf[(size_t)(b * HWDIM + hw) * CDIM + c] = z[i];
}

// ---- row L2 norms: one warp per row of 128 floats ----
__global__ void row_norms(const float* __restrict__ X, float* __restrict__ out, int P) {
    int gw   = (blockIdx.x * blockDim.x + threadIdx.x) >> 5;
    int lane = threadIdx.x & 31;
    if (gw >= P) return;
    float4 v = *reinterpret_cast<const float4*>(X + (size_t)gw * CDIM + lane * 4);
    float s = v.x * v.x + v.y * v.y + v.z * v.z + v.w * v.w;
#pragma unroll
    for (int off = 16; off; off >>= 1) s += __shfl_xor_sync(0xffffffffu, s, off);
    if (lane == 0) out[gw] = s;
}

// ---- fused streaming GEMM + online logsumexp ----
// For each row p of X: lse_p = logsumexp_q( alpha * max(||x_p||^2 + ||y_q||^2 - 2 x_p.y_q, 0) )
// Block: TILE_P = RPT*16 rows, streams over Q in chunks of 128 columns.
// 256 threads = 16 col-groups (tx) x 16 row-groups (ty); thread micro-tile RPT x 8.
// Columns per thread: q = tx + 16*i (strided -> conflict-free scalar LDS on Y).
template <int RPT>
__global__ void __launch_bounds__(256, 1)
lse_gemm(const float* __restrict__ X,  const float* __restrict__ Xsq,
         const float* __restrict__ Y,  const float* __restrict__ Ysq,
         const float* __restrict__ lsg, float* __restrict__ out,
         int P, int Q)
{
    constexpr int TILE_P  = RPT * 16;
    constexpr int XSTRIDE = TILE_P + 4;   // multiple of 4 -> float4-aligned rows
    constexpr int YSTRIDE = 129;          // odd -> conflict-free strided scalar reads

    extern __shared__ float sm[];
    float* Xs    = sm;                        // [CDIM][XSTRIDE], Xs[k][p]
    float* Yt    = sm + CDIM * XSTRIDE;       // [CDIM][YSTRIDE], Yt[k][q]
    float* ysq_s = Yt + CDIM * YSTRIDE;       // [128]

    const int tid = threadIdx.x;
    const int tx  = tid & 15;
    const int ty  = tid >> 4;
    const int p0  = blockIdx.x * TILE_P;

    const float ls    = lsg[0];
    const float alpha = -0.5f * __expf(-2.0f * ls);   // -1/(2*exp(ls)^2)

    // Load + transpose X tile into smem (once per block)
#pragma unroll
    for (int it = 0; it < TILE_P / 8; ++it) {
        int idx = tid + it * 256;
        int c4 = idx & 31, p = idx >> 5;
        float4 v = *reinterpret_cast<const float4*>(X + (size_t)(p0 + p) * CDIM + c4 * 4);
        Xs[(c4 * 4 + 0) * XSTRIDE + p] = v.x;
        Xs[(c4 * 4 + 1) * XSTRIDE + p] = v.y;
        Xs[(c4 * 4 + 2) * XSTRIDE + p] = v.z;
        Xs[(c4 * 4 + 3) * XSTRIDE + p] = v.w;
    }

    float xsq[RPT], m[RPT], s[RPT];
#pragma unroll
    for (int r = 0; r < RPT; ++r) {
        xsq[r] = Xsq[p0 + ty * RPT + r];
        m[r] = -1e30f;
        s[r] = 0.0f;
    }

    for (int q0 = 0; q0 < Q; q0 += 128) {
        __syncthreads();   // previous chunk fully consumed
        // Load + transpose Y chunk [128 x C] into Yt[k][q]
#pragma unroll
        for (int it = 0; it < 16; ++it) {
            int idx = tid + it * 256;
            int c4 = idx & 31, q = idx >> 5;
            float4 v = *reinterpret_cast<const float4*>(Y + (size_t)(q0 + q) * CDIM + c4 * 4);
            Yt[(c4 * 4 + 0) * YSTRIDE + q] = v.x;
            Yt[(c4 * 4 + 1) * YSTRIDE + q] = v.y;
            Yt[(c4 * 4 + 2) * YSTRIDE + q] = v.z;
            Yt[(c4 * 4 + 3) * YSTRIDE + q] = v.w;
        }
        if (tid < 128) ysq_s[tid] = Ysq[q0 + tid];
        __syncthreads();

        unsigned long long acc[RPT][4];
#pragma unroll
        for (int r = 0; r < RPT; ++r)
#pragma unroll
            for (int c = 0; c < 4; ++c) acc[r][c] = 0ull;

#pragma unroll 4
        for (int k = 0; k < CDIM; ++k) {
            // y pairs: pair j covers columns (tx + 32j, tx + 32j + 16)
            unsigned long long yp[4];
#pragma unroll
            for (int j = 0; j < 4; ++j) {
                float a = Yt[k * YSTRIDE + tx + 32 * j];
                float b = Yt[k * YSTRIDE + tx + 32 * j + 16];
                yp[j] = pack2(a, b);
            }
            const float* xrow = &Xs[k * XSTRIDE + ty * RPT];
            float xv[RPT];
#pragma unroll
            for (int r4 = 0; r4 < RPT / 4; ++r4) {
                float4 t = *reinterpret_cast<const float4*>(xrow + r4 * 4);
                xv[r4 * 4 + 0] = t.x; xv[r4 * 4 + 1] = t.y;
                xv[r4 * 4 + 2] = t.z; xv[r4 * 4 + 3] = t.w;
            }
#pragma unroll
            for (int r = 0; r < RPT; ++r) {
                unsigned long long xd = pack2(xv[r], xv[r]);
                fma2(acc[r][0], xd, yp[0]);
                fma2(acc[r][1], xd, yp[1]);
                fma2(acc[r][2], xd, yp[2]);
                fma2(acc[r][3], xd, yp[3]);
            }
        }

        // epilogue: dist -> A -> online logsumexp merge
        float yq0[4], yq1[4];
#pragma unroll
        for (int j = 0; j < 4; ++j) {
            yq0[j] = ysq_s[tx + 32 * j];
            yq1[j] = ysq_s[tx + 32 * j + 16];
        }
#pragma unroll
        for (int r = 0; r < RPT; ++r) {
            float vv[8];
            float cm = -1e30f;
#pragma unroll
            for (int j = 0; j < 4; ++j) {
                float d0, d1;
                unpack2(acc[r][j], d0, d1);
                float dist0 = fmaxf(xsq[r] + yq0[j] - 2.0f * d0, 0.0f);
                float dist1 = fmaxf(xsq[r] + yq1[j] - 2.0f * d1, 0.0f);
                float a0 = alpha * dist0;
                float a1 = alpha * dist1;
                vv[2 * j]     = a0;
                vv[2 * j + 1] = a1;
                cm = fmaxf(cm, fmaxf(a0, a1));
            }
            float nm  = fmaxf(m[r], cm);
            float acc_s = s[r] * __expf(m[r] - nm);
#pragma unroll
            for (int i = 0; i < 8; ++i) acc_s += __expf(vv[i] - nm);
            m[r] = nm;
            s[r] = acc_s;
        }
    }

    // merge (m, s) across the 16 col-group threads (same ty = same half-warp)
#pragma unroll
    for (int r = 0; r < RPT; ++r) {
        float mm = m[r], ss = s[r];
#pragma unroll
        for (int off = 8; off >= 1; off >>= 1) {
            float om = __shfl_xor_sync(0xffffffffu, mm, off);
            float os = __shfl_xor_sync(0xffffffffu, ss, off);
            float nm = fmaxf(mm, om);
            ss = ss * __expf(mm - nm) + os * __expf(om - nm);
            mm = nm;
        }
        if (tx == 0) out[p0 + ty * RPT + r] = mm + __logf(ss);
    }
}

// ---- final reduction to the two scalar losses ----
__global__ void finalize(const float* __restrict__ rowl, const float* __restrict__ coll,
                         const float* __restrict__ lsg, float* __restrict__ out) {
    __shared__ double red[256];
    int which = blockIdx.x;
    int n = (which == 0) ? NTOK : MCODE;
    const float* src = (which == 0) ? rowl : coll;
    double a = 0.0;
    for (int i = threadIdx.x; i < n; i += 256) a += (double)src[i];
    red[threadIdx.x] = a;
    __syncthreads();
    for (int st = 128; st; st >>= 1) {
        if (threadIdx.x < st) red[threadIdx.x] += red[threadIdx.x + st];
        __syncthreads();
    }
    if (threadIdx.x == 0) {
        float ls  = lsg[0];
        float cst = 0.5f * (float)CDIM * (2.0f * ls - 1.0f);
        float lg  = (which == 0) ? logf((float)MCODE) : logf((float)NTOK);
        out[which] = (float)(-(red[0] / (double)n)) + cst + lg;
    }
}

extern "C" void kernel_launch(void* const* d_in, const int* in_sizes, int n_in,
                              void* d_out, int out_size) {
    (void)in_sizes; (void)n_in; (void)out_size;
    const float* z   = (const float*)d_in[0];
    const float* e   = (const float*)d_in[1];
    const float* lsg = (const float*)d_in[2];
    float* out = (float*)d_out;

    float *zf, *zsq, *esq, *rowl, *coll;
    cudaGetSymbolAddress((void**)&zf,   g_zf);
    cudaGetSymbolAddress((void**)&zsq,  g_zsq);
    cudaGetSymbolAddress((void**)&esq,  g_esq);
    cudaGetSymbolAddress((void**)&rowl, g_rowlse);
    cudaGetSymbolAddress((void**)&coll, g_collse);

    // dynamic smem sizes (floats): CDIM*XSTRIDE + CDIM*YSTRIDE + 128
    const int SMEM8 = (CDIM * (128 + 4) + CDIM * 129 + 128) * (int)sizeof(float); // 134144
    const int SMEM4 = (CDIM * (64 + 4)  + CDIM * 129 + 128) * (int)sizeof(float); // 101376
    cudaFuncSetAttribute(lse_gemm<8>, cudaFuncAttributeMaxDynamicSharedMemorySize, SMEM8);
    cudaFuncSetAttribute(lse_gemm<4>, cudaFuncAttributeMaxDynamicSharedMemorySize, SMEM4);

    build_zf<<<(BDIM * CDIM * HWDIM + 255) / 256, 256>>>(z, zf);
    row_norms<<<(NTOK * 32 + 255) / 256, 256>>>(zf, zsq, NTOK);
    row_norms<<<(MCODE * 32 + 255) / 256, 256>>>(e, esq, MCODE);

    // pass 1: rows = z tokens (N), stream over codes (M) -> lse over axis=1
    lse_gemm<8><<<NTOK / 128, 256, SMEM8>>>(zf, zsq, e, esq, lsg, rowl, NTOK, MCODE);
    // pass 2: rows = codes (M), stream over tokens (N) -> lse over axis=0
    lse_gemm<4><<<MCODE / 64, 256, SMEM4>>>(e, esq, zf, zsq, lsg, coll, MCODE, NTOK);

    finalize<<<2, 256>>>(rowl, coll, lsg, out);
}

// round 3
// speedup vs baseline: 2.8417x; 2.8417x over previous
#include <cuda_runtime.h>
#include <cuda_bf16.h>
#include <math.h>
#include <stdint.h>

// Problem constants (dataset-fixed: z[16,128,32,32], e[8192,128], log_sigma[1])
#define NTOK  16384
#define MCODE 8192
#define CDIM  128
#define BDIM  16
#define HWDIM 1024

// ---------------- device scratch (no runtime allocation) ----------------
__device__ float         g_zf [(size_t)NTOK * CDIM];
__device__ __nv_bfloat16 g_zhi[(size_t)NTOK * CDIM];
__device__ __nv_bfloat16 g_zlo[(size_t)NTOK * CDIM];
__device__ __nv_bfloat16 g_ehi[(size_t)MCODE * CDIM];
__device__ __nv_bfloat16 g_elo[(size_t)MCODE * CDIM];
__device__ float g_zsq[NTOK], g_esq[MCODE];
__device__ float g_p1m[NTOK],      g_p1s[NTOK];        // pass1: 1 split
__device__ float g_p2m[2 * MCODE], g_p2s[2 * MCODE];   // pass2: 2 splits

// ---------------- helpers ----------------
__device__ __forceinline__ uint32_t smem_u32(const void* p) {
    uint32_t a;
    asm("{ .reg .u64 t; cvta.to.shared.u64 t, %1; cvt.u32.u64 %0, t; }" : "=r"(a) : "l"(p));
    return a;
}
__device__ __forceinline__ float ex2f(float x) {
    float r; asm("ex2.approx.ftz.f32 %0, %1;" : "=f"(r) : "f"(x)); return r;
}
__device__ __forceinline__ void cpasync16(uint32_t dst, const void* src) {
    asm volatile("cp.async.cg.shared.global [%0], [%1], 16;" :: "r"(dst), "l"(src) : "memory");
}
__device__ __forceinline__ void cpcommit() {
    asm volatile("cp.async.commit_group;" ::: "memory");
}
template <int N> __device__ __forceinline__ void cpwait() {
    asm volatile("cp.async.wait_group %0;" :: "n"(N) : "memory");
}
__device__ __forceinline__ void ldsm_x4(uint32_t* r, uint32_t addr) {
    asm volatile("ldmatrix.sync.aligned.m8n8.x4.shared.b16 {%0,%1,%2,%3}, [%4];"
                 : "=r"(r[0]), "=r"(r[1]), "=r"(r[2]), "=r"(r[3]) : "r"(addr));
}
__device__ __forceinline__ void mma16816(float* d, const uint32_t* a, const uint32_t* b) {
    asm volatile(
        "mma.sync.aligned.m16n8k16.row.col.f32.bf16.bf16.f32 "
        "{%0,%1,%2,%3}, {%4,%5,%6,%7}, {%8,%9}, {%0,%1,%2,%3};"
        : "+f"(d[0]), "+f"(d[1]), "+f"(d[2]), "+f"(d[3])
        : "r"(a[0]), "r"(a[1]), "r"(a[2]), "r"(a[3]), "r"(b[0]), "r"(b[1]));
}

// ---------------- smem layout (byte offsets from 1024-aligned base) ----------------
// Tile rows hold 256 bf16: [hi 128 | lo 128] = 512 bytes/row, XOR-swizzled 16B chunks.
#define OFF_X      0                     /* 128 rows * 512B = 64KB   */
#define OFF_Y(b)   (65536 + (b) * 65536) /* two 64KB Y buffers       */
#define OFF_YSQ    196608                /* 2 * 128 floats           */
#define OFF_REDM   197632                /* 4 * 128 floats           */
#define OFF_REDS   (197632 + 2048)       /* 4 * 128 floats           */
#define SMEM_BYTES (197632 + 4096 + 1024)

// swizzled byte offset of 16B chunk c (0..31) in row r
__device__ __forceinline__ uint32_t swz(int r, int c) {
    return (uint32_t)(r * 512 + ((c >> 3) << 7) + ((((c & 7) ^ (r & 7))) << 4));
}

// async: gmem [128 x 128] hi + lo -> smem tile (row = [hi|lo], swizzled)
__device__ __forceinline__ void tile_async(const __nv_bfloat16* __restrict__ hi,
                                           const __nv_bfloat16* __restrict__ lo,
                                           uint32_t dstbase, int tid) {
#pragma unroll
    for (int it = 0; it < 16; ++it) {
        int u = tid + it * 256;        // 0..4095
        int r = u >> 5, c = u & 31;
        const void* src = (c < 16) ? (const void*)(hi + (size_t)r * CDIM + c * 8)
                                   : (const void*)(lo + (size_t)r * CDIM + (c - 16) * 8);
        cpasync16(dstbase + swz(r, c), src);
    }
}

// ---------------- prep kernels ----------------
__global__ void build_zf(const float* __restrict__ z, float* __restrict__ zf) {
    int i = blockIdx.x * 256 + threadIdx.x;
    if (i >= BDIM * CDIM * HWDIM) return;
    int hw = i & (HWDIM - 1);
    int bc = i >> 10;
    int c  = bc & (CDIM - 1);
    int b  = bc >> 7;
    zf[(size_t)(b * HWDIM + hw) * CDIM + c] = z[i];
}

__global__ void bf16split(const float* __restrict__ x, __nv_bfloat16* __restrict__ hi,
                          __nv_bfloat16* __restrict__ lo, int n) {
    int i = blockIdx.x * 256 + threadIdx.x;
    if (i >= n) return;
    float v = x[i];
    __nv_bfloat16 h = __float2bfloat16(v);
    hi[i] = h;
    lo[i] = __float2bfloat16(v - __bfloat162float(h));
}

__global__ void row_norms(const float* __restrict__ X, float* __restrict__ out, int P) {
    int gw = (blockIdx.x * blockDim.x + threadIdx.x) >> 5;
    int lane = threadIdx.x & 31;
    if (gw >= P) return;
    float4 v = *reinterpret_cast<const float4*>(X + (size_t)gw * CDIM + lane * 4);
    float s = v.x * v.x + v.y * v.y + v.z * v.z + v.w * v.w;
#pragma unroll
    for (int off = 16; off; off >>= 1) s += __shfl_xor_sync(0xffffffffu, s, off);
    if (lane == 0) out[gw] = s;
}

// ---------------- fused bf16-split MMA + row logsumexp ----------------
// Per CTA: 128 X-rows, stream Y in 128-col tiles. 8 warps = 2(m) x 4(n);
// warp tile 64x32 via m16n8k16. Hi/lo split: D = Xhi.Yhi + Xhi.Ylo + Xlo.Yhi.
__global__ void __launch_bounds__(256, 1)
lse_mma(const __nv_bfloat16* __restrict__ Xhi, const __nv_bfloat16* __restrict__ Xlo,
        const float* __restrict__ Xsq,
        const __nv_bfloat16* __restrict__ Yhi, const __nv_bfloat16* __restrict__ Ylo,
        const float* __restrict__ Ysq,
        const float* __restrict__ lsg,
        float* __restrict__ outm, float* __restrict__ outs,
        int ntiles)
{
    extern __shared__ char sraw[];
    uint32_t sb0  = smem_u32(sraw);
    uint32_t base = (sb0 + 1023) & ~1023u;
    char* smem = sraw + (base - sb0);
    float* ysq_s = reinterpret_cast<float*>(smem + OFF_YSQ);
    float* redm  = reinterpret_cast<float*>(smem + OFF_REDM);
    float* reds  = reinterpret_cast<float*>(smem + OFF_REDS);

    const int tid = threadIdx.x;
    const int l   = tid & 31;
    const int w   = tid >> 5;
    const int wm  = w & 1;         // row half (64)
    const int wn  = w >> 1;        // col quarter (32)
    const int p0  = blockIdx.x * 128;
    const int q0  = blockIdx.y * ntiles * 128;

    const float ls     = lsg[0];
    const float alpha2 = -0.5f * __expf(-2.0f * ls) * 1.4426950408889634f;  // alpha/ln2
    const float beta2  = -2.0f * alpha2;

    // prologue: X tile + Y tile 0 (one cp.async group)
    tile_async(Xhi + (size_t)p0 * CDIM, Xlo + (size_t)p0 * CDIM, base + OFF_X, tid);
    tile_async(Yhi + (size_t)q0 * CDIM, Ylo + (size_t)q0 * CDIM, base + OFF_Y(0), tid);
    cpcommit();
    if (tid < 128) ysq_s[tid] = alpha2 * Ysq[q0 + tid];

    // per-thread row constants (8 accumulator rows owned by this thread)
    float base2[8];
#pragma unroll
    for (int mf = 0; mf < 4; ++mf)
#pragma unroll
        for (int h = 0; h < 2; ++h)
            base2[mf * 2 + h] = alpha2 * Xsq[p0 + wm * 64 + mf * 16 + (l >> 2) + 8 * h];

    float mS[8], sS[8];
#pragma unroll
    for (int i = 0; i < 8; ++i) { mS[i] = -1e30f; sS[i] = 0.0f; }

    // per-lane ldmatrix address constants
    const int rx  = l & 7;
    const int aco = l >> 4;           // A chunk offset (0/1)
    const int bco = (l >> 3) & 1;     // B chunk offset (0/1)
    uint32_t arow[4], brow[2];
#pragma unroll
    for (int mf = 0; mf < 4; ++mf)
        arow[mf] = (uint32_t)((wm * 64 + mf * 16 + (l & 15)) * 512);
#pragma unroll
    for (int g = 0; g < 2; ++g)
        brow[g] = (uint32_t)((wn * 32 + g * 16 + (l & 7) + ((l >> 4) << 3)) * 512);

    for (int t = 0; t < ntiles; ++t) {
        const int cur = t & 1;
        if (t + 1 < ntiles) {
            const size_t q1 = (size_t)(q0 + (t + 1) * 128);
            tile_async(Yhi + q1 * CDIM, Ylo + q1 * CDIM, base + OFF_Y(cur ^ 1), tid);
            cpcommit();
            if (tid < 128) ysq_s[(cur ^ 1) * 128 + tid] = alpha2 * Ysq[q1 + tid];
            cpwait<1>();
        } else {
            cpwait<0>();
        }
        __syncthreads();

        float acc[4][4][4];
#pragma unroll
        for (int mf = 0; mf < 4; ++mf)
#pragma unroll
            for (int nf = 0; nf < 4; ++nf)
#pragma unroll
                for (int k = 0; k < 4; ++k) acc[mf][nf][k] = 0.0f;

        const uint32_t Ab = base + OFF_X;
        const uint32_t Bb = base + OFF_Y(cur);
        const int paT[3] = {0, 0, 1}, pbT[3] = {0, 1, 0};
#pragma unroll 1
        for (int p = 0; p < 3; ++p) {
            const int ca = paT[p] * 16, cb = pbT[p] * 16;
#pragma unroll
            for (int ks = 0; ks < 8; ++ks) {
                uint32_t a[4][4], b[2][4];
                const int cA = ca + ks * 2 + aco;
                const uint32_t sa = (uint32_t)(((cA >> 3) << 7) | (((cA & 7) ^ rx) << 4));
#pragma unroll
                for (int mf = 0; mf < 4; ++mf) ldsm_x4(a[mf], Ab + arow[mf] + sa);
                const int cB = cb + ks * 2 + bco;
                const uint32_t sb = (uint32_t)(((cB >> 3) << 7) | (((cB & 7) ^ rx) << 4));
#pragma unroll
                for (int g = 0; g < 2; ++g) ldsm_x4(b[g], Bb + brow[g] + sb);
#pragma unroll
                for (int mf = 0; mf < 4; ++mf)
#pragma unroll
                    for (int g = 0; g < 2; ++g) {
                        mma16816(acc[mf][2 * g],     a[mf], &b[g][0]);
                        mma16816(acc[mf][2 * g + 1], a[mf], &b[g][2]);
                    }
            }
        }

        // epilogue: 64 values/thread -> online (m, s) per owned row (log2 domain)
        const float* tc = ysq_s + cur * 128;
        float tcv[4][2];
#pragma unroll
        for (int nf = 0; nf < 4; ++nf)
#pragma unroll
            for (int j = 0; j < 2; ++j)
                tcv[nf][j] = tc[wn * 32 + nf * 8 + 2 * (l & 3) + j];
#pragma unroll
        for (int mf = 0; mf < 4; ++mf)
#pragma unroll
            for (int h = 0; h < 2; ++h) {
                const int ri = mf * 2 + h;
                float v[8], cm = -1e30f;
#pragma unroll
                for (int nf = 0; nf < 4; ++nf)
#pragma unroll
                    for (int j = 0; j < 2; ++j) {
                        float d   = acc[mf][nf][2 * h + j];
                        float val = fminf(fmaf(d, beta2, tcv[nf][j]) + base2[ri], 0.0f);
                        v[nf * 2 + j] = val;
                        cm = fmaxf(cm, val);
                    }
                float nm = fmaxf(mS[ri], cm);
                float aS = sS[ri] * ex2f(mS[ri] - nm);
#pragma unroll
                for (int i2 = 0; i2 < 8; ++i2) aS += ex2f(v[i2] - nm);
                mS[ri] = nm;
                sS[ri] = aS;
            }
        __syncthreads();
    }

    // merge across the 4 lanes of each quad (they share rows, own different cols)
#pragma unroll
    for (int ri = 0; ri < 8; ++ri) {
        float m = mS[ri], s = sS[ri];
#pragma unroll
        for (int off = 1; off <= 2; off <<= 1) {
            float om = __shfl_xor_sync(0xffffffffu, m, off);
            float os = __shfl_xor_sync(0xffffffffu, s, off);
            float nm = fmaxf(m, om);
            s = s * ex2f(m - nm) + os * ex2f(om - nm);
            m = nm;
        }
        mS[ri] = m; sS[ri] = s;
    }
    if ((l & 3) == 0) {
#pragma unroll
        for (int mf = 0; mf < 4; ++mf)
#pragma unroll
            for (int h = 0; h < 2; ++h) {
                int rloc = wm * 64 + mf * 16 + (l >> 2) + 8 * h;
                redm[wn * 128 + rloc] = mS[mf * 2 + h];
                reds[wn * 128 + rloc] = sS[mf * 2 + h];
            }
    }
    __syncthreads();
    if (tid < 128) {
        float m = redm[tid], s = reds[tid];
#pragma unroll
        for (int g = 1; g < 4; ++g) {
            float m2 = redm[g * 128 + tid], s2 = reds[g * 128 + tid];
            float nm = fmaxf(m, m2);
            s = s * ex2f(m - nm) + s2 * ex2f(m2 - nm);
            m = nm;
        }
        int gi = blockIdx.y * (gridDim.x * 128) + p0 + tid;
        outm[gi] = m;
        outs[gi] = s;
    }
}

// ---------------- finalize: merge splits, lse, mean, constants ----------------
__global__ void finalize(const float* __restrict__ lsg, float* __restrict__ out) {
    __shared__ double red[256];
    const int which = blockIdx.x;
    const int P      = (which == 0) ? NTOK : MCODE;
    const int splits = (which == 0) ? 1 : 2;
    const float* pm  = (which == 0) ? g_p1m : g_p2m;
    const float* ps  = (which == 0) ? g_p1s : g_p2s;
    double acc = 0.0;
    for (int i = threadIdx.x; i < P; i += 256) {
        float m = pm[i], s = ps[i];
        for (int sp = 1; sp < splits; ++sp) {
            float m2 = pm[sp * P + i], s2 = ps[sp * P + i];
            float mm = fmaxf(m, m2);
            s = s * ex2f(m - mm) + s2 * ex2f(m2 - mm);
            m = mm;
        }
        acc += 0.6931471805599453 * ((double)m + (double)__log2f(s));
    }
    red[threadIdx.x] = acc;
    __syncthreads();
    for (int st = 128; st; st >>= 1) {
        if (threadIdx.x < st) red[threadIdx.x] += red[threadIdx.x + st];
        __syncthreads();
    }
    if (threadIdx.x == 0) {
        float ls  = lsg[0];
        float cst = 0.5f * (float)CDIM * (2.0f * ls - 1.0f);
        float lg  = (which == 0) ? logf((float)MCODE) : logf((float)NTOK);
        out[which] = (float)(-(red[0] / (double)P)) + cst + lg;
    }
}

// ---------------- launch ----------------
extern "C" void kernel_launch(void* const* d_in, const int* in_sizes, int n_in,
                              void* d_out, int out_size) {
    (void)in_sizes; (void)n_in; (void)out_size;
    const float* z   = (const float*)d_in[0];
    const float* e   = (const float*)d_in[1];
    const float* lsg = (const float*)d_in[2];
    float* out = (float*)d_out;

    float *zf, *zsq, *esq, *p1m, *p1s, *p2m, *p2s;
    __nv_bfloat16 *zhi, *zlo, *ehi, *elo;
    cudaGetSymbolAddress((void**)&zf,  g_zf);
    cudaGetSymbolAddress((void**)&zhi, g_zhi);
    cudaGetSymbolAddress((void**)&zlo, g_zlo);
    cudaGetSymbolAddress((void**)&ehi, g_ehi);
    cudaGetSymbolAddress((void**)&elo, g_elo);
    cudaGetSymbolAddress((void**)&zsq, g_zsq);
    cudaGetSymbolAddress((void**)&esq, g_esq);
    cudaGetSymbolAddress((void**)&p1m, g_p1m);
    cudaGetSymbolAddress((void**)&p1s, g_p1s);
    cudaGetSymbolAddress((void**)&p2m, g_p2m);
    cudaGetSymbolAddress((void**)&p2s, g_p2s);

    cudaFuncSetAttribute(lse_mma, cudaFuncAttributeMaxDynamicSharedMemorySize, SMEM_BYTES);

    build_zf<<<(BDIM * CDIM * HWDIM + 255) / 256, 256>>>(z, zf);
    bf16split<<<(NTOK * CDIM + 255) / 256, 256>>>(zf, zhi, zlo, NTOK * CDIM);
    bf16split<<<(MCODE * CDIM + 255) / 256, 256>>>(e, ehi, elo, MCODE * CDIM);
    row_norms<<<(NTOK * 32 + 255) / 256, 256>>>(zf, zsq, NTOK);
    row_norms<<<(MCODE * 32 + 255) / 256, 256>>>(e, esq, MCODE);

    // pass 1: rows = z tokens, stream codes (Q=8192 -> 64 tiles), 128 CTAs
    lse_mma<<<dim3(NTOK / 128, 1), 256, SMEM_BYTES>>>(zhi, zlo, zsq, ehi, elo, esq,
                                                      lsg, p1m, p1s, MCODE / 128);
    // pass 2: rows = codes, stream tokens in 2 splits (64 tiles each), 128 CTAs
    lse_mma<<<dim3(MCODE / 128, 2), 256, SMEM_BYTES>>>(ehi, elo, esq, zhi, zlo, zsq,
                                                       lsg, p2m, p2s, (NTOK / 2) / 128);

    finalize<<<2, 256>>>(lsg, out);
}

// round 4
// speedup vs baseline: 3.7891x; 1.3334x over previous
#include <cuda_runtime.h>
#include <cuda_bf16.h>
#include <math.h>
#include <stdint.h>

// Problem constants (dataset-fixed: z[16,128,32,32], e[8192,128], log_sigma[1])
#define NTOK  16384
#define MCODE 8192
#define CDIM  128
#define BDIM  16
#define HWDIM 1024

// ---------------- device scratch (no runtime allocation) ----------------
__device__ float         g_zf [(size_t)NTOK * CDIM];
__device__ __nv_bfloat16 g_zhi[(size_t)NTOK * CDIM];
__device__ __nv_bfloat16 g_zlo[(size_t)NTOK * CDIM];
__device__ __nv_bfloat16 g_ehi[(size_t)MCODE * CDIM];
__device__ __nv_bfloat16 g_elo[(size_t)MCODE * CDIM];
__device__ float g_zsq[NTOK], g_esq[MCODE];
__device__ float g_p1m[NTOK],      g_p1s[NTOK];        // pass1: 1 split
__device__ float g_p2m[2 * MCODE], g_p2s[2 * MCODE];   // pass2: 2 splits

// ---------------- helpers ----------------
__device__ __forceinline__ uint32_t smem_u32(const void* p) {
    uint32_t a;
    asm("{ .reg .u64 t; cvta.to.shared.u64 t, %1; cvt.u32.u64 %0, t; }" : "=r"(a) : "l"(p));
    return a;
}
__device__ __forceinline__ float ex2f(float x) {
    float r; asm("ex2.approx.ftz.f32 %0, %1;" : "=f"(r) : "f"(x)); return r;
}
__device__ __forceinline__ void cpasync16(uint32_t dst, const void* src) {
    asm volatile("cp.async.cg.shared.global [%0], [%1], 16;" :: "r"(dst), "l"(src) : "memory");
}
__device__ __forceinline__ void cpcommit() {
    asm volatile("cp.async.commit_group;" ::: "memory");
}
template <int N> __device__ __forceinline__ void cpwait() {
    asm volatile("cp.async.wait_group %0;" :: "n"(N) : "memory");
}
__device__ __forceinline__ void ldsm_x4(uint32_t* r, uint32_t addr) {
    asm volatile("ldmatrix.sync.aligned.m8n8.x4.shared.b16 {%0,%1,%2,%3}, [%4];"
                 : "=r"(r[0]), "=r"(r[1]), "=r"(r[2]), "=r"(r[3]) : "r"(addr));
}
__device__ __forceinline__ void mma16816(float* d, const uint32_t* a, const uint32_t* b) {
    asm volatile(
        "mma.sync.aligned.m16n8k16.row.col.f32.bf16.bf16.f32 "
        "{%0,%1,%2,%3}, {%4,%5,%6,%7}, {%8,%9}, {%0,%1,%2,%3};"
        : "+f"(d[0]), "+f"(d[1]), "+f"(d[2]), "+f"(d[3])
        : "r"(a[0]), "r"(a[1]), "r"(a[2]), "r"(a[3]), "r"(b[0]), "r"(b[1]));
}

// ---------------- smem layout (byte offsets from 1024-aligned base) ----------------
// X rows hold 256 bf16: [hi 128 | lo 128] = 512B/row. Y rows hold 128 bf16 (hi) = 256B/row.
#define OFF_X      0                     /* 128 * 512B = 64KB        */
#define OFF_Y(b)   (65536 + (b) * 32768) /* two 32KB Y (hi) buffers  */
#define OFF_YSQ    131072                /* 2 * 128 floats           */
#define OFF_REDM   132096                /* 4 * 128 floats           */
#define OFF_REDS   (132096 + 2048)       /* 4 * 128 floats           */
#define SMEM_BYTES (132096 + 4096 + 1024)

// swizzled byte offset of 16B chunk c in a row of `rowB` bytes
__device__ __forceinline__ uint32_t swzc(int c, int r) {
    return (uint32_t)(((c >> 3) << 7) + ((((c & 7) ^ (r & 7))) << 4));
}

// ---------------- prep kernels ----------------
__global__ void build_zf(const float* __restrict__ z, float* __restrict__ zf) {
    int i = blockIdx.x * 256 + threadIdx.x;
    if (i >= BDIM * CDIM * HWDIM) return;
    int hw = i & (HWDIM - 1);
    int bc = i >> 10;
    int c  = bc & (CDIM - 1);
    int b  = bc >> 7;
    zf[(size_t)(b * HWDIM + hw) * CDIM + c] = z[i];
}

__global__ void bf16split(const float* __restrict__ x, __nv_bfloat16* __restrict__ hi,
                          __nv_bfloat16* __restrict__ lo, int n) {
    int i = blockIdx.x * 256 + threadIdx.x;
    if (i >= n) return;
    float v = x[i];
    __nv_bfloat16 h = __float2bfloat16(v);
    hi[i] = h;
    lo[i] = __float2bfloat16(v - __bfloat162float(h));
}

__global__ void row_norms(const float* __restrict__ X, float* __restrict__ out, int P) {
    int gw = (blockIdx.x * blockDim.x + threadIdx.x) >> 5;
    int lane = threadIdx.x & 31;
    if (gw >= P) return;
    float4 v = *reinterpret_cast<const float4*>(X + (size_t)gw * CDIM + lane * 4);
    float s = v.x * v.x + v.y * v.y + v.z * v.z + v.w * v.w;
#pragma unroll
    for (int off = 16; off; off >>= 1) s += __shfl_xor_sync(0xffffffffu, s, off);
    if (lane == 0) out[gw] = s;
}

// ---------------- fused bf16-split MMA + row logsumexp ----------------
// D = (Xhi + Xlo) . Yhi^T  (2-term split; X-side exact to ~2^-17, Y rounded to bf16).
// 512 threads = 16 warps = 4(m) x 4(n); warp tile 32x32 via m16n8k16.
__global__ void __launch_bounds__(512, 1)
lse_mma(const __nv_bfloat16* __restrict__ Xhi, const __nv_bfloat16* __restrict__ Xlo,
        const float* __restrict__ Xsq,
        const __nv_bfloat16* __restrict__ Yhi,
        const float* __restrict__ Ysq,
        const float* __restrict__ lsg,
        float* __restrict__ outm, float* __restrict__ outs,
        int ntiles)
{
    extern __shared__ char sraw[];
    uint32_t sb0  = smem_u32(sraw);
    uint32_t base = (sb0 + 1023) & ~1023u;
    char* smem = sraw + (base - sb0);
    float* ysq_s = reinterpret_cast<float*>(smem + OFF_YSQ);
    float* redm  = reinterpret_cast<float*>(smem + OFF_REDM);
    float* reds  = reinterpret_cast<float*>(smem + OFF_REDS);

    const int tid = threadIdx.x;
    const int l   = tid & 31;
    const int w   = tid >> 5;
    const int wm  = w & 3;         // row block (32)
    const int wn  = w >> 2;        // col block (32)
    const int p0  = blockIdx.x * 128;
    const int q0  = blockIdx.y * ntiles * 128;

    const float ls     = lsg[0];
    const float alpha2 = -0.5f * __expf(-2.0f * ls) * 1.4426950408889634f;  // alpha/ln2
    const float beta2  = -2.0f * alpha2;

    // prologue: X tile (hi|lo) + Y tile 0 (hi)
#pragma unroll
    for (int it = 0; it < 8; ++it) {
        int u = tid + it * 512;        // 0..4095
        int r = u >> 5, c = u & 31;
        const void* src = (c < 16) ? (const void*)(Xhi + (size_t)(p0 + r) * CDIM + c * 8)
                                   : (const void*)(Xlo + (size_t)(p0 + r) * CDIM + (c - 16) * 8);
        cpasync16(base + OFF_X + r * 512 + swzc(c, r), src);
    }
#pragma unroll
    for (int it = 0; it < 4; ++it) {
        int u = tid + it * 512;        // 0..2047
        int r = u >> 4, c = u & 15;
        cpasync16(base + OFF_Y(0) + r * 256 + swzc(c, r),
                  Yhi + (size_t)(q0 + r) * CDIM + c * 8);
    }
    cpcommit();
    if (tid < 128) ysq_s[tid] = alpha2 * Ysq[q0 + tid];

    // per-thread row constants (4 accumulator rows owned by this thread)
    float base2[4];
#pragma unroll
    for (int mf = 0; mf < 2; ++mf)
#pragma unroll
        for (int h = 0; h < 2; ++h)
            base2[mf * 2 + h] = alpha2 * Xsq[p0 + wm * 32 + mf * 16 + (l >> 2) + 8 * h];

    float mS[4], sS[4];
#pragma unroll
    for (int i = 0; i < 4; ++i) { mS[i] = -1e30f; sS[i] = 0.0f; }

    // per-lane ldmatrix address constants
    const int rx  = l & 7;
    const int aco = l >> 4;           // A chunk offset (0/1)
    const int bco = (l >> 3) & 1;     // B chunk offset (0/1)
    uint32_t arow[2], brow[2];
#pragma unroll
    for (int mf = 0; mf < 2; ++mf)
        arow[mf] = (uint32_t)((wm * 32 + mf * 16 + (l & 15)) * 512);
#pragma unroll
    for (int g = 0; g < 2; ++g)
        brow[g] = (uint32_t)((wn * 32 + g * 16 + (l & 7) + ((l >> 4) << 3)) * 256);

    for (int t = 0; t < ntiles; ++t) {
        const int cur = t & 1;
        if (t + 1 < ntiles) {
            const size_t q1 = (size_t)(q0 + (t + 1) * 128);
#pragma unroll
            for (int it = 0; it < 4; ++it) {
                int u = tid + it * 512;
                int r = u >> 4, c = u & 15;
                cpasync16(base + OFF_Y(cur ^ 1) + r * 256 + swzc(c, r),
                          Yhi + (q1 + r) * CDIM + c * 8);
            }
            cpcommit();
            if (tid < 128) ysq_s[(cur ^ 1) * 128 + tid] = alpha2 * Ysq[q1 + tid];
            cpwait<1>();
        } else {
            cpwait<0>();
        }
        __syncthreads();

        float acc[2][4][4];
#pragma unroll
        for (int mf = 0; mf < 2; ++mf)
#pragma unroll
            for (int nf = 0; nf < 4; ++nf)
#pragma unroll
                for (int k = 0; k < 4; ++k) acc[mf][nf][k] = 0.0f;

        const uint32_t Ab = base + OFF_X;
        const uint32_t Bb = base + OFF_Y(cur);
#pragma unroll 1
        for (int p = 0; p < 2; ++p) {
            const int ca = p * 16;    // hi chunks 0-15, lo chunks 16-31
#pragma unroll
            for (int ks = 0; ks < 8; ++ks) {
                uint32_t a[2][4], b[2][4];
                const int cA = ca + ks * 2 + aco;
                const uint32_t sa = swzc(cA, rx);
#pragma unroll
                for (int mf = 0; mf < 2; ++mf) ldsm_x4(a[mf], Ab + arow[mf] + sa);
                const int cB = ks * 2 + bco;
                const uint32_t sb = swzc(cB, rx);
#pragma unroll
                for (int g = 0; g < 2; ++g) ldsm_x4(b[g], Bb + brow[g] + sb);
#pragma unroll
                for (int mf = 0; mf < 2; ++mf)
#pragma unroll
                    for (int g = 0; g < 2; ++g) {
                        mma16816(acc[mf][2 * g],     a[mf], &b[g][0]);
                        mma16816(acc[mf][2 * g + 1], a[mf], &b[g][2]);
                    }
            }
        }

        // epilogue: 32 values/thread -> online (m, s) per owned row (log2 domain)
        const float* tc = ysq_s + cur * 128;
        float tcv[4][2];
#pragma unroll
        for (int nf = 0; nf < 4; ++nf)
#pragma unroll
            for (int j = 0; j < 2; ++j)
                tcv[nf][j] = tc[wn * 32 + nf * 8 + 2 * (l & 3) + j];
#pragma unroll
        for (int mf = 0; mf < 2; ++mf)
#pragma unroll
            for (int h = 0; h < 2; ++h) {
                const int ri = mf * 2 + h;
                float v[8], cm = -1e30f;
#pragma unroll
                for (int nf = 0; nf < 4; ++nf)
#pragma unroll
                    for (int j = 0; j < 2; ++j) {
                        float d   = acc[mf][nf][2 * h + j];
                        float val = fminf(fmaf(d, beta2, tcv[nf][j]) + base2[ri], 0.0f);
                        v[nf * 2 + j] = val;
                        cm = fmaxf(cm, val);
                    }
                float nm = fmaxf(mS[ri], cm);
                float aS = sS[ri] * ex2f(mS[ri] - nm);
#pragma unroll
                for (int i2 = 0; i2 < 8; ++i2) aS += ex2f(v[i2] - nm);
                mS[ri] = nm;
                sS[ri] = aS;
            }
        __syncthreads();
    }

    // merge across the 4 lanes of each quad (same rows, different cols)
#pragma unroll
    for (int ri = 0; ri < 4; ++ri) {
        float m = mS[ri], s = sS[ri];
#pragma unroll
        for (int off = 1; off <= 2; off <<= 1) {
            float om = __shfl_xor_sync(0xffffffffu, m, off);
            float os = __shfl_xor_sync(0xffffffffu, s, off);
            float nm = fmaxf(m, om);
            s = s * ex2f(m - nm) + os * ex2f(om - nm);
            m = nm;
        }
        mS[ri] = m; sS[ri] = s;
    }
    if ((l & 3) == 0) {
#pragma unroll
        for (int mf = 0; mf < 2; ++mf)
#pragma unroll
            for (int h = 0; h < 2; ++h) {
                int rloc = wm * 32 + mf * 16 + (l >> 2) + 8 * h;
                redm[wn * 128 + rloc] = mS[mf * 2 + h];
                reds[wn * 128 + rloc] = sS[mf * 2 + h];
            }
    }
    __syncthreads();
    if (tid < 128) {
        float m = redm[tid], s = reds[tid];
#pragma unroll
        for (int g = 1; g < 4; ++g) {
            float m2 = redm[g * 128 + tid], s2 = reds[g * 128 + tid];
            float nm = fmaxf(m, m2);
            s = s * ex2f(m - nm) + s2 * ex2f(m2 - nm);
            m = nm;
        }
        int gi = blockIdx.y * (gridDim.x * 128) + p0 + tid;
        outm[gi] = m;
        outs[gi] = s;
    }
}

// ---------------- finalize: merge splits, lse, mean, constants ----------------
__global__ void finalize(const float* __restrict__ lsg, float* __restrict__ out) {
    __shared__ double red[256];
    const int which = blockIdx.x;
    const int P      = (which == 0) ? NTOK : MCODE;
    const int splits = (which == 0) ? 1 : 2;
    const float* pm  = (which == 0) ? g_p1m : g_p2m;
    const float* ps  = (which == 0) ? g_p1s : g_p2s;
    double acc = 0.0;
    for (int i = threadIdx.x; i < P; i += 256) {
        float m = pm[i], s = ps[i];
        for (int sp = 1; sp < splits; ++sp) {
            float m2 = pm[sp * P + i], s2 = ps[sp * P + i];
            float mm = fmaxf(m, m2);
            s = s * ex2f(m - mm) + s2 * ex2f(m2 - mm);
            m = mm;
        }
        acc += 0.6931471805599453 * ((double)m + (double)__log2f(s));
    }
    red[threadIdx.x] = acc;
    __syncthreads();
    for (int st = 128; st; st >>= 1) {
        if (threadIdx.x < st) red[threadIdx.x] += red[threadIdx.x + st];
        __syncthreads();
    }
    if (threadIdx.x == 0) {
        float ls  = lsg[0];
        float cst = 0.5f * (float)CDIM * (2.0f * ls - 1.0f);
        float lg  = (which == 0) ? logf((float)MCODE) : logf((float)NTOK);
        out[which] = (float)(-(red[0] / (double)P)) + cst + lg;
    }
}

// ---------------- launch ----------------
extern "C" void kernel_launch(void* const* d_in, const int* in_sizes, int n_in,
                              void* d_out, int out_size) {
    (void)in_sizes; (void)n_in; (void)out_size;
    const float* z   = (const float*)d_in[0];
    const float* e   = (const float*)d_in[1];
    const float* lsg = (const float*)d_in[2];
    float* out = (float*)d_out;

    float *zf, *zsq, *esq, *p1m, *p1s, *p2m, *p2s;
    __nv_bfloat16 *zhi, *zlo, *ehi, *elo;
    cudaGetSymbolAddress((void**)&zf,  g_zf);
    cudaGetSymbolAddress((void**)&zhi, g_zhi);
    cudaGetSymbolAddress((void**)&zlo, g_zlo);
    cudaGetSymbolAddress((void**)&ehi, g_ehi);
    cudaGetSymbolAddress((void**)&elo, g_elo);
    cudaGetSymbolAddress((void**)&zsq, g_zsq);
    cudaGetSymbolAddress((void**)&esq, g_esq);
    cudaGetSymbolAddress((void**)&p1m, g_p1m);
    cudaGetSymbolAddress((void**)&p1s, g_p1s);
    cudaGetSymbolAddress((void**)&p2m, g_p2m);
    cudaGetSymbolAddress((void**)&p2s, g_p2s);

    cudaFuncSetAttribute(lse_mma, cudaFuncAttributeMaxDynamicSharedMemorySize, SMEM_BYTES);

    build_zf<<<(BDIM * CDIM * HWDIM + 255) / 256, 256>>>(z, zf);
    bf16split<<<(NTOK * CDIM + 255) / 256, 256>>>(zf, zhi, zlo, NTOK * CDIM);
    bf16split<<<(MCODE * CDIM + 255) / 256, 256>>>(e, ehi, elo, MCODE * CDIM);
    row_norms<<<(NTOK * 32 + 255) / 256, 256>>>(zf, zsq, NTOK);
    row_norms<<<(MCODE * 32 + 255) / 256, 256>>>(e, esq, MCODE);

    // pass 1: rows = z tokens (X = z hi/lo), stream codes hi (64 tiles), 128 CTAs
    lse_mma<<<dim3(NTOK / 128, 1), 512, SMEM_BYTES>>>(zhi, zlo, zsq, ehi, esq,
                                                      lsg, p1m, p1s, MCODE / 128);
    // pass 2: rows = codes (X = e hi/lo), stream tokens hi in 2 splits, 128 CTAs
    lse_mma<<<dim3(MCODE / 128, 2), 512, SMEM_BYTES>>>(ehi, elo, esq, zhi, zsq,
                                                       lsg, p2m, p2s, (NTOK / 2) / 128);

    finalize<<<2, 256>>>(lsg, out);
}

// round 5
// speedup vs baseline: 6.8891x; 1.8181x over previous
#include <cuda_runtime.h>
#include <cuda_bf16.h>
#include <math.h>
#include <stdint.h>

// Problem constants (dataset-fixed: z[16,128,32,32], e[8192,128], log_sigma[1])
#define NTOK  16384
#define MCODE 8192
#define CDIM  128
#define BDIM  16
#define HWDIM 1024
#define PTILES (NTOK / 128)     /* 128 CTAs, one per 128-row z tile */
#define QTILES (MCODE / 128)    /* 64 streamed e tiles */

// ---------------- device scratch (no runtime allocation) ----------------
__device__ __nv_bfloat16 g_zhi[(size_t)NTOK * CDIM];
__device__ __nv_bfloat16 g_zlo[(size_t)NTOK * CDIM];
__device__ __nv_bfloat16 g_ehi[(size_t)MCODE * CDIM];
__device__ float g_zsq[NTOK], g_esq[MCODE];
__device__ float g_rm[NTOK],  g_rs[NTOK];                    // row LSE states (final)
__device__ float g_cpm[(size_t)PTILES * MCODE];              // col partials [p][q]
__device__ float g_cps[(size_t)PTILES * MCODE];
__device__ float g_cm[MCODE], g_cs[MCODE];                   // merged col states

// ---------------- helpers ----------------
__device__ __forceinline__ uint32_t smem_u32(const void* p) {
    uint32_t a;
    asm("{ .reg .u64 t; cvta.to.shared.u64 t, %1; cvt.u32.u64 %0, t; }" : "=r"(a) : "l"(p));
    return a;
}
__device__ __forceinline__ float ex2f(float x) {
    float r; asm("ex2.approx.ftz.f32 %0, %1;" : "=f"(r) : "f"(x)); return r;
}
// (m,s) logsumexp-state merge with ONE ex2:  state <- state (+) (m2,s2)
__device__ __forceinline__ void merge_ms(float& m, float& s, float m2, float s2) {
    float e = ex2f(-fabsf(m - m2));
    if (m >= m2) { s = s + s2 * e; }
    else         { s = s2 + s * e; m = m2; }
}
__device__ __forceinline__ void cpasync16(uint32_t dst, const void* src) {
    asm volatile("cp.async.cg.shared.global [%0], [%1], 16;" :: "r"(dst), "l"(src) : "memory");
}
__device__ __forceinline__ void cpcommit() {
    asm volatile("cp.async.commit_group;" ::: "memory");
}
template <int N> __device__ __forceinline__ void cpwait() {
    asm volatile("cp.async.wait_group %0;" :: "n"(N) : "memory");
}
__device__ __forceinline__ void ldsm_x4(uint32_t* r, uint32_t addr) {
    asm volatile("ldmatrix.sync.aligned.m8n8.x4.shared.b16 {%0,%1,%2,%3}, [%4];"
                 : "=r"(r[0]), "=r"(r[1]), "=r"(r[2]), "=r"(r[3]) : "r"(addr));
}
__device__ __forceinline__ void mma16816(float* d, const uint32_t* a, const uint32_t* b) {
    asm volatile(
        "mma.sync.aligned.m16n8k16.row.col.f32.bf16.bf16.f32 "
        "{%0,%1,%2,%3}, {%4,%5,%6,%7}, {%8,%9}, {%0,%1,%2,%3};"
        : "+f"(d[0]), "+f"(d[1]), "+f"(d[2]), "+f"(d[3])
        : "r"(a[0]), "r"(a[1]), "r"(a[2]), "r"(a[3]), "r"(b[0]), "r"(b[1]));
}
__device__ __forceinline__ uint32_t packbf2(float a, float b) {
    __nv_bfloat162 t = __floats2bfloat162_rn(a, b);
    return *reinterpret_cast<uint32_t*>(&t);
}

// ---------------- smem layout (byte offsets from 1024-aligned base) ----------------
// X rows: [hi 128 | lo 128] bf16 = 512B/row. Y rows: 128 bf16 (hi) = 256B/row.
#define OFF_X      0                     /* 128*512 = 64KB            */
#define OFF_Y(b)   (65536 + (b) * 32768) /* two 32KB Y buffers        */
#define OFF_YSQ    131072                /* 2*128 floats              */
#define OFF_COL    132096                /* 4*128*2 floats = 4KB      */
#define OFF_REDM   136192                /* 4*128 floats              */
#define OFF_REDS   138240                /* 4*128 floats              */
#define SMEM_BYTES (138240 + 2048 + 1024)

__device__ __forceinline__ uint32_t swzc(int c, int r) {
    return (uint32_t)(((c >> 3) << 7) + ((((c & 7) ^ (r & 7))) << 4));
}

// ---------------- fused prep: z transpose + bf16 hi/lo split + row norms ----------------
// z[B,C,H,W] -> zhi/zlo[n][c], zsq[n];  n = b*1024 + hw
__global__ void fuse_z(const float* __restrict__ z,
                       __nv_bfloat16* __restrict__ zhi, __nv_bfloat16* __restrict__ zlo,
                       float* __restrict__ zsq) {
    __shared__ float tile[32 * 129];    // [hw][c], stride 129
    const int t   = threadIdx.x;
    const int b   = blockIdx.x >> 5;
    const int hw0 = (blockIdx.x & 31) * 32;
    const int lane = t & 31;
#pragma unroll
    for (int it = 0; it < 16; ++it) {
        int c = (t >> 5) + it * 8;
        tile[lane * 129 + c] = z[(size_t)b * (CDIM * HWDIM) + (size_t)c * HWDIM + hw0 + lane];
    }
    __syncthreads();
    const int tloc = t >> 3;
    const int c0   = (t & 7) * 16;
    const int n    = b * HWDIM + hw0 + tloc;
    float sq = 0.0f;
    uint32_t hp[8], lp[8];
#pragma unroll
    for (int i = 0; i < 8; ++i) {
        float a = tile[tloc * 129 + c0 + 2 * i];
        float c = tile[tloc * 129 + c0 + 2 * i + 1];
        sq += a * a + c * c;
        float ah = __bfloat162float(__float2bfloat16(a));
        float ch = __bfloat162float(__float2bfloat16(c));
        hp[i] = packbf2(a, c);                  // rn conversion of each
        lp[i] = packbf2(a - ah, c - ch);
    }
    uint4* dh = reinterpret_cast<uint4*>(zhi + (size_t)n * CDIM + c0);
    uint4* dl = reinterpret_cast<uint4*>(zlo + (size_t)n * CDIM + c0);
    dh[0] = make_uint4(hp[0], hp[1], hp[2], hp[3]);
    dh[1] = make_uint4(hp[4], hp[5], hp[6], hp[7]);
    dl[0] = make_uint4(lp[0], lp[1], lp[2], lp[3]);
    dl[1] = make_uint4(lp[4], lp[5], lp[6], lp[7]);
#pragma unroll
    for (int off = 1; off <= 4; off <<= 1) sq += __shfl_xor_sync(0xffffffffu, sq, off);
    if ((t & 7) == 0) zsq[n] = sq;
}

// e[M,C] -> ehi, esq (warp per row)
__global__ void fuse_e(const float* __restrict__ e,
                       __nv_bfloat16* __restrict__ ehi, float* __restrict__ esq) {
    const int w    = (blockIdx.x * blockDim.x + threadIdx.x) >> 5;
    const int lane = threadIdx.x & 31;
    if (w >= MCODE) return;
    float4 v = *reinterpret_cast<const float4*>(e + (size_t)w * CDIM + lane * 4);
    float sq = v.x * v.x + v.y * v.y + v.z * v.z + v.w * v.w;
    uint2 h = make_uint2(packbf2(v.x, v.y), packbf2(v.z, v.w));
    *reinterpret_cast<uint2*>(ehi + (size_t)w * CDIM + lane * 4) = h;
#pragma unroll
    for (int off = 16; off; off >>= 1) sq += __shfl_xor_sync(0xffffffffu, sq, off);
    if (lane == 0) esq[w] = sq;
}

// ---------------- single-pass: D computed once, row LSE + col partials ----------------
// D = (Xhi + Xlo) . Yhi^T ; 512 threads = 16 warps = 4(wm) x 4(wn), warp tile 32x32.
__global__ void __launch_bounds__(512, 1)
lse_single(const __nv_bfloat16* __restrict__ Xhi, const __nv_bfloat16* __restrict__ Xlo,
           const float* __restrict__ Xsq,
           const __nv_bfloat16* __restrict__ Yhi, const float* __restrict__ Ysq,
           const float* __restrict__ lsg,
           float* __restrict__ rowm, float* __restrict__ rows,
           float* __restrict__ cpm,  float* __restrict__ cps)
{
    extern __shared__ char sraw[];
    uint32_t sb0  = smem_u32(sraw);
    uint32_t base = (sb0 + 1023) & ~1023u;
    char* smem = sraw + (base - sb0);
    float* ysq_s = reinterpret_cast<float*>(smem + OFF_YSQ);
    float* colsm = reinterpret_cast<float*>(smem + OFF_COL);    // [4 wm][128][2]
    float* redm  = reinterpret_cast<float*>(smem + OFF_REDM);
    float* reds  = reinterpret_cast<float*>(smem + OFF_REDS);

    const int tid = threadIdx.x;
    const int l   = tid & 31;
    const int w   = tid >> 5;
    const int wm  = w & 3;
    const int wn  = w >> 2;
    const int p0  = blockIdx.x * 128;

    const float ls     = lsg[0];
    const float alpha2 = -0.5f * __expf(-2.0f * ls) * 1.4426950408889634f;  // alpha/ln2
    const float beta2  = -2.0f * alpha2;

    // prologue: X tile (hi|lo) + Y tile 0
#pragma unroll
    for (int it = 0; it < 8; ++it) {
        int u = tid + it * 512;
        int r = u >> 5, c = u & 31;
        const void* src = (c < 16) ? (const void*)(Xhi + (size_t)(p0 + r) * CDIM + c * 8)
                                   : (const void*)(Xlo + (size_t)(p0 + r) * CDIM + (c - 16) * 8);
        cpasync16(base + OFF_X + r * 512 + swzc(c, r), src);
    }
#pragma unroll
    for (int it = 0; it < 4; ++it) {
        int u = tid + it * 512;
        int r = u >> 4, c = u & 15;
        cpasync16(base + OFF_Y(0) + r * 256 + swzc(c, r), Yhi + (size_t)r * CDIM + c * 8);
    }
    cpcommit();
    if (tid < 128) ysq_s[tid] = alpha2 * Ysq[tid];

    float base2[4];
#pragma unroll
    for (int mf = 0; mf < 2; ++mf)
#pragma unroll
        for (int h = 0; h < 2; ++h)
            base2[mf * 2 + h] = alpha2 * Xsq[p0 + wm * 32 + mf * 16 + (l >> 2) + 8 * h];

    float mS[4], sS[4];
#pragma unroll
    for (int i = 0; i < 4; ++i) { mS[i] = -1e30f; sS[i] = 0.0f; }

    const int rx  = l & 7;
    const int aco = l >> 4;
    const int bco = (l >> 3) & 1;
    uint32_t arow[2], brow[2];
#pragma unroll
    for (int mf = 0; mf < 2; ++mf)
        arow[mf] = (uint32_t)((wm * 32 + mf * 16 + (l & 15)) * 512);
#pragma unroll
    for (int g = 0; g < 2; ++g)
        brow[g] = (uint32_t)((wn * 32 + g * 16 + (l & 7) + ((l >> 4) << 3)) * 256);

    for (int t = 0; t < QTILES; ++t) {
        const int cur = t & 1;
        if (t + 1 < QTILES) {
            const size_t q1 = (size_t)(t + 1) * 128;
#pragma unroll
            for (int it = 0; it < 4; ++it) {
                int u = tid + it * 512;
                int r = u >> 4, c = u & 15;
                cpasync16(base + OFF_Y(cur ^ 1) + r * 256 + swzc(c, r),
                          Yhi + (q1 + r) * CDIM + c * 8);
            }
            cpcommit();
            if (tid < 128) ysq_s[(cur ^ 1) * 128 + tid] = alpha2 * Ysq[q1 + tid];
            cpwait<1>();
        } else {
            cpwait<0>();
        }
        __syncthreads();   // Y(t) fully resident; colsm(t-1) consumed

        float acc[2][4][4];
#pragma unroll
        for (int mf = 0; mf < 2; ++mf)
#pragma unroll
            for (int nf = 0; nf < 4; ++nf)
#pragma unroll
                for (int k = 0; k < 4; ++k) acc[mf][nf][k] = 0.0f;

        const uint32_t Ab = base + OFF_X;
        const uint32_t Bb = base + OFF_Y(cur);
#pragma unroll
        for (int ks = 0; ks < 8; ++ks) {
            uint32_t b[2][4];
            const uint32_t sb = swzc(ks * 2 + bco, rx);
#pragma unroll
            for (int g = 0; g < 2; ++g) ldsm_x4(b[g], Bb + brow[g] + sb);
#pragma unroll
            for (int p = 0; p < 2; ++p) {
                uint32_t a[2][4];
                const uint32_t sa = swzc(p * 16 + ks * 2 + aco, rx);
#pragma unroll
                for (int mf = 0; mf < 2; ++mf) ldsm_x4(a[mf], Ab + arow[mf] + sa);
#pragma unroll
                for (int mf = 0; mf < 2; ++mf)
#pragma unroll
                    for (int g = 0; g < 2; ++g) {
                        mma16816(acc[mf][2 * g],     a[mf], &b[g][0]);
                        mma16816(acc[mf][2 * g + 1], a[mf], &b[g][2]);
                    }
            }
        }

        // ---- epilogue: v = clamp(A/ln2, <=0); one exp per element feeds BOTH LSEs ----
        const float* tc = ysq_s + cur * 128;
        float tcv[4][2];
#pragma unroll
        for (int nf = 0; nf < 4; ++nf)
#pragma unroll
            for (int j = 0; j < 2; ++j)
                tcv[nf][j] = tc[wn * 32 + nf * 8 + 2 * (l & 3) + j];

        float g = -1e30f;
#pragma unroll
        for (int mf = 0; mf < 2; ++mf)
#pragma unroll
            for (int nf = 0; nf < 4; ++nf)
#pragma unroll
                for (int k = 0; k < 4; ++k) {
                    const int ri = mf * 2 + (k >> 1);
                    float v = fminf(base2[ri] + fmaf(acc[mf][nf][k], beta2, tcv[nf][k & 1]), 0.0f);
                    acc[mf][nf][k] = v;
                    g = fmaxf(g, v);
                }
#pragma unroll
        for (int mf = 0; mf < 2; ++mf)
#pragma unroll
            for (int nf = 0; nf < 4; ++nf)
#pragma unroll
                for (int k = 0; k < 4; ++k)
                    acc[mf][nf][k] = ex2f(acc[mf][nf][k] - g);

        // row sums (scale g)
#pragma unroll
        for (int ri = 0; ri < 4; ++ri) {
            const int mf = ri >> 1, h = ri & 1;
            float P = 0.0f;
#pragma unroll
            for (int nf = 0; nf < 4; ++nf) P += acc[mf][nf][2 * h] + acc[mf][nf][2 * h + 1];
            merge_ms(mS[ri], sS[ri], g, P);
        }
        // col sums (scale g) + shfl-merge over the 8 row-lanes
        float cm[8], cs[8];
#pragma unroll
        for (int nf = 0; nf < 4; ++nf)
#pragma unroll
            for (int j = 0; j < 2; ++j) {
                float Q = 0.0f;
#pragma unroll
                for (int mf = 0; mf < 2; ++mf) Q += acc[mf][nf][j] + acc[mf][nf][2 + j];
                cm[nf * 2 + j] = g;
                cs[nf * 2 + j] = Q;
            }
#pragma unroll
        for (int off = 4; off <= 16; off <<= 1)
#pragma unroll
            for (int i = 0; i < 8; ++i) {
                float m2 = __shfl_xor_sync(0xffffffffu, cm[i], off);
                float s2 = __shfl_xor_sync(0xffffffffu, cs[i], off);
                merge_ms(cm[i], cs[i], m2, s2);
            }
        if (l < 4) {
#pragma unroll
            for (int nf = 0; nf < 4; ++nf)
#pragma unroll
                for (int j = 0; j < 2; ++j) {
                    int c = wn * 32 + nf * 8 + 2 * l + j;
                    colsm[(wm * 128 + c) * 2 + 0] = cm[nf * 2 + j];
                    colsm[(wm * 128 + c) * 2 + 1] = cs[nf * 2 + j];
                }
        }
        __syncthreads();   // colsm ready; all warps past MMA(t) -> next prefetch safe
        if (tid < 128) {
            float m = colsm[tid * 2], s = colsm[tid * 2 + 1];
#pragma unroll
            for (int gq = 1; gq < 4; ++gq)
                merge_ms(m, s, colsm[(gq * 128 + tid) * 2], colsm[(gq * 128 + tid) * 2 + 1]);
            cpm[(size_t)blockIdx.x * MCODE + t * 128 + tid] = m;
            cps[(size_t)blockIdx.x * MCODE + t * 128 + tid] = s;
        }
    }

    // row finalization: merge quad lanes (cols), then across wn warps
#pragma unroll
    for (int ri = 0; ri < 4; ++ri) {
#pragma unroll
        for (int off = 1; off <= 2; off <<= 1) {
            float m2 = __shfl_xor_sync(0xffffffffu, mS[ri], off);
            float s2 = __shfl_xor_sync(0xffffffffu, sS[ri], off);
            merge_ms(mS[ri], sS[ri], m2, s2);
        }
    }
    __syncthreads();
    if ((l & 3) == 0) {
#pragma unroll
        for (int mf = 0; mf < 2; ++mf)
#pragma unroll
            for (int h = 0; h < 2; ++h) {
                int rloc = wm * 32 + mf * 16 + (l >> 2) + 8 * h;
                redm[wn * 128 + rloc] = mS[mf * 2 + h];
                reds[wn * 128 + rloc] = sS[mf * 2 + h];
            }
    }
    __syncthreads();
    if (tid < 128) {
        float m = redm[tid], s = reds[tid];
#pragma unroll
        for (int gq = 1; gq < 4; ++gq) merge_ms(m, s, redm[gq * 128 + tid], reds[gq * 128 + tid]);
        rowm[p0 + tid] = m;
        rows[p0 + tid] = s;
    }
}

// ---------------- merge column partials: 128 states per q ----------------
__global__ void colmerge(const float* __restrict__ cpm, const float* __restrict__ cps,
                         float* __restrict__ cm, float* __restrict__ cs) {
    const int q = blockIdx.x * blockDim.x + threadIdx.x;
    if (q >= MCODE) return;
    float m[4], s[4];
#pragma unroll
    for (int c = 0; c < 4; ++c) { m[c] = -1e30f; s[c] = 0.0f; }
    for (int p = 0; p < PTILES; p += 4) {
#pragma unroll
        for (int c = 0; c < 4; ++c)
            merge_ms(m[c], s[c], __ldg(cpm + (size_t)(p + c) * MCODE + q),
                                 __ldg(cps + (size_t)(p + c) * MCODE + q));
    }
    merge_ms(m[0], s[0], m[1], s[1]);
    merge_ms(m[2], s[2], m[3], s[3]);
    merge_ms(m[0], s[0], m[2], s[2]);
    cm[q] = m[0];
    cs[q] = s[0];
}

// ---------------- finalize: mean of LSEs + constants ----------------
__global__ void finalize(const float* __restrict__ lsg, float* __restrict__ out) {
    __shared__ double red[256];
    const int which = blockIdx.x;
    const int P     = (which == 0) ? NTOK : MCODE;
    const float* pm = (which == 0) ? g_rm : g_cm;
    const float* ps = (which == 0) ? g_rs : g_cs;
    double acc = 0.0;
    for (int i = threadIdx.x; i < P; i += 256)
        acc += 0.6931471805599453 * ((double)pm[i] + (double)__log2f(ps[i]));
    red[threadIdx.x] = acc;
    __syncthreads();
    for (int st = 128; st; st >>= 1) {
        if (threadIdx.x < st) red[threadIdx.x] += red[threadIdx.x + st];
        __syncthreads();
    }
    if (threadIdx.x == 0) {
        float ls  = lsg[0];
        float cst = 0.5f * (float)CDIM * (2.0f * ls - 1.0f);
        float lg  = (which == 0) ? logf((float)MCODE) : logf((float)NTOK);
        out[which] = (float)(-(red[0] / (double)P)) + cst + lg;
    }
}

// ---------------- launch ----------------
extern "C" void kernel_launch(void* const* d_in, const int* in_sizes, int n_in,
                              void* d_out, int out_size) {
    (void)in_sizes; (void)n_in; (void)out_size;
    const float* z   = (const float*)d_in[0];
    const float* e   = (const float*)d_in[1];
    const float* lsg = (const float*)d_in[2];
    float* out = (float*)d_out;

    float *zsq, *esq, *rm, *rs, *cpm, *cps, *cm, *cs;
    __nv_bfloat16 *zhi, *zlo, *ehi;
    cudaGetSymbolAddress((void**)&zhi, g_zhi);
    cudaGetSymbolAddress((void**)&zlo, g_zlo);
    cudaGetSymbolAddress((void**)&ehi, g_ehi);
    cudaGetSymbolAddress((void**)&zsq, g_zsq);
    cudaGetSymbolAddress((void**)&esq, g_esq);
    cudaGetSymbolAddress((void**)&rm,  g_rm);
    cudaGetSymbolAddress((void**)&rs,  g_rs);
    cudaGetSymbolAddress((void**)&cpm, g_cpm);
    cudaGetSymbolAddress((void**)&cps, g_cps);
    cudaGetSymbolAddress((void**)&cm,  g_cm);
    cudaGetSymbolAddress((void**)&cs,  g_cs);

    cudaFuncSetAttribute(lse_single, cudaFuncAttributeMaxDynamicSharedMemorySize, SMEM_BYTES);

    fuse_z<<<512, 256>>>(z, zhi, zlo, zsq);
    fuse_e<<<MCODE / 8, 256>>>(e, ehi, esq);

    lse_single<<<PTILES, 512, SMEM_BYTES>>>(zhi, zlo, zsq, ehi, esq, lsg,
                                            rm, rs, cpm, cps);

    colmerge<<<MCODE / 256, 256>>>(cpm, cps, cm, cs);
    finalize<<<2, 256>>>(lsg, out);
}

// round 6
// speedup vs baseline: 7.0478x; 1.0230x over previous
#include <cuda_runtime.h>
#include <cuda_bf16.h>
#include <math.h>
#include <stdint.h>

// Problem constants (dataset-fixed: z[16,128,32,32], e[8192,128], log_sigma[1])
#define NTOK  16384
#define MCODE 8192
#define CDIM  128
#define BDIM  16
#define HWDIM 1024
#define PTILES (NTOK / 128)     /* 128 CTAs, one per 128-row z tile */
#define QTILES (MCODE / 128)    /* 64 streamed e tiles */

// ---------------- device scratch (no runtime allocation) ----------------
__device__ __nv_bfloat16 g_zhi[(size_t)NTOK * CDIM];
__device__ __nv_bfloat16 g_zlo[(size_t)NTOK * CDIM];
__device__ __nv_bfloat16 g_ehi[(size_t)MCODE * CDIM];
__device__ float g_zsq[NTOK], g_esq[MCODE];
__device__ float g_rm[NTOK],  g_rs[NTOK];                    // row LSE states (final)
__device__ float g_cpm[(size_t)PTILES * MCODE];              // col partials [p][q]
__device__ float g_cps[(size_t)PTILES * MCODE];
__device__ float g_cm[MCODE], g_cs[MCODE];                   // merged col states

// ---------------- helpers ----------------
__device__ __forceinline__ uint32_t smem_u32(const void* p) {
    uint32_t a;
    asm("{ .reg .u64 t; cvta.to.shared.u64 t, %1; cvt.u32.u64 %0, t; }" : "=r"(a) : "l"(p));
    return a;
}
__device__ __forceinline__ float ex2f(float x) {
    float r; asm("ex2.approx.ftz.f32 %0, %1;" : "=f"(r) : "f"(x)); return r;
}
// (m,s) logsumexp-state merge with ONE ex2:  state <- state (+) (m2,s2)
__device__ __forceinline__ void merge_ms(float& m, float& s, float m2, float s2) {
    float e = ex2f(-fabsf(m - m2));
    if (m >= m2) { s = s + s2 * e; }
    else         { s = s2 + s * e; m = m2; }
}
__device__ __forceinline__ void cpasync16(uint32_t dst, const void* src) {
    asm volatile("cp.async.cg.shared.global [%0], [%1], 16;" :: "r"(dst), "l"(src) : "memory");
}
__device__ __forceinline__ void cpcommit() {
    asm volatile("cp.async.commit_group;" ::: "memory");
}
template <int N> __device__ __forceinline__ void cpwait() {
    asm volatile("cp.async.wait_group %0;" :: "n"(N) : "memory");
}
__device__ __forceinline__ void ldsm_x4(uint32_t* r, uint32_t addr) {
    asm volatile("ldmatrix.sync.aligned.m8n8.x4.shared.b16 {%0,%1,%2,%3}, [%4];"
                 : "=r"(r[0]), "=r"(r[1]), "=r"(r[2]), "=r"(r[3]) : "r"(addr));
}
__device__ __forceinline__ void mma16816(float* d, const uint32_t* a, const uint32_t* b) {
    asm volatile(
        "mma.sync.aligned.m16n8k16.row.col.f32.bf16.bf16.f32 "
        "{%0,%1,%2,%3}, {%4,%5,%6,%7}, {%8,%9}, {%0,%1,%2,%3};"
        : "+f"(d[0]), "+f"(d[1]), "+f"(d[2]), "+f"(d[3])
        : "r"(a[0]), "r"(a[1]), "r"(a[2]), "r"(a[3]), "r"(b[0]), "r"(b[1]));
}
__device__ __forceinline__ uint32_t packbf2(float a, float b) {
    __nv_bfloat162 t = __floats2bfloat162_rn(a, b);
    return *reinterpret_cast<uint32_t*>(&t);
}

// ---------------- smem layout (byte offsets from 1024-aligned base) ----------------
#define OFF_X      0                     /* 128*512 = 64KB            */
#define OFF_Y(b)   (65536 + (b) * 32768) /* two 32KB Y buffers        */
#define OFF_YSQ    131072                /* 2*128 floats              */
#define OFF_COL    132096                /* 4*128*2 floats = 4KB      */
#define OFF_REDM   136192                /* 4*128 floats              */
#define OFF_REDS   138240                /* 4*128 floats              */
#define SMEM_BYTES (138240 + 2048 + 1024)

__device__ __forceinline__ uint32_t swzc(int c, int r) {
    return (uint32_t)(((c >> 3) << 7) + ((((c & 7) ^ (r & 7))) << 4));
}

// ---------------- fused prep: z transpose + bf16 hi/lo split + row norms ----------------
__global__ void fuse_z(const float* __restrict__ z,
                       __nv_bfloat16* __restrict__ zhi, __nv_bfloat16* __restrict__ zlo,
                       float* __restrict__ zsq) {
    __shared__ float tile[32 * 129];
    const int t   = threadIdx.x;
    const int b   = blockIdx.x >> 5;
    const int hw0 = (blockIdx.x & 31) * 32;
    const int lane = t & 31;
#pragma unroll
    for (int it = 0; it < 16; ++it) {
        int c = (t >> 5) + it * 8;
        tile[lane * 129 + c] = z[(size_t)b * (CDIM * HWDIM) + (size_t)c * HWDIM + hw0 + lane];
    }
    __syncthreads();
    const int tloc = t >> 3;
    const int c0   = (t & 7) * 16;
    const int n    = b * HWDIM + hw0 + tloc;
    float sq = 0.0f;
    uint32_t hp[8], lp[8];
#pragma unroll
    for (int i = 0; i < 8; ++i) {
        float a = tile[tloc * 129 + c0 + 2 * i];
        float c = tile[tloc * 129 + c0 + 2 * i + 1];
        sq += a * a + c * c;
        float ah = __bfloat162float(__float2bfloat16(a));
        float ch = __bfloat162float(__float2bfloat16(c));
        hp[i] = packbf2(a, c);
        lp[i] = packbf2(a - ah, c - ch);
    }
    uint4* dh = reinterpret_cast<uint4*>(zhi + (size_t)n * CDIM + c0);
    uint4* dl = reinterpret_cast<uint4*>(zlo + (size_t)n * CDIM + c0);
    dh[0] = make_uint4(hp[0], hp[1], hp[2], hp[3]);
    dh[1] = make_uint4(hp[4], hp[5], hp[6], hp[7]);
    dl[0] = make_uint4(lp[0], lp[1], lp[2], lp[3]);
    dl[1] = make_uint4(lp[4], lp[5], lp[6], lp[7]);
#pragma unroll
    for (int off = 1; off <= 4; off <<= 1) sq += __shfl_xor_sync(0xffffffffu, sq, off);
    if ((t & 7) == 0) zsq[n] = sq;
}

__global__ void fuse_e(const float* __restrict__ e,
                       __nv_bfloat16* __restrict__ ehi, float* __restrict__ esq) {
    const int w    = (blockIdx.x * blockDim.x + threadIdx.x) >> 5;
    const int lane = threadIdx.x & 31;
    if (w >= MCODE) return;
    float4 v = *reinterpret_cast<const float4*>(e + (size_t)w * CDIM + lane * 4);
    float sq = v.x * v.x + v.y * v.y + v.z * v.z + v.w * v.w;
    uint2 h = make_uint2(packbf2(v.x, v.y), packbf2(v.z, v.w));
    *reinterpret_cast<uint2*>(ehi + (size_t)w * CDIM + lane * 4) = h;
#pragma unroll
    for (int off = 16; off; off >>= 1) sq += __shfl_xor_sync(0xffffffffu, sq, off);
    if (lane == 0) esq[w] = sq;
}

// ---------------- single-pass: D computed once, row LSE + col partials ----------------
// D = (Xhi + Xlo) . Yhi^T ; 512 threads = 16 warps = 4(wm) x 4(wn), warp tile 32x32.
// Epilogue uses a warp-common log2-scale g: cross-lane reductions are plain adds.
__global__ void __launch_bounds__(512, 1)
lse_single(const __nv_bfloat16* __restrict__ Xhi, const __nv_bfloat16* __restrict__ Xlo,
           const float* __restrict__ Xsq,
           const __nv_bfloat16* __restrict__ Yhi, const float* __restrict__ Ysq,
           const float* __restrict__ lsg,
           float* __restrict__ rowm, float* __restrict__ rows,
           float* __restrict__ cpm,  float* __restrict__ cps)
{
    extern __shared__ char sraw[];
    uint32_t sb0  = smem_u32(sraw);
    uint32_t base = (sb0 + 1023) & ~1023u;
    char* smem = sraw + (base - sb0);
    float* ysq_s = reinterpret_cast<float*>(smem + OFF_YSQ);
    float* colsm = reinterpret_cast<float*>(smem + OFF_COL);
    float* redm  = reinterpret_cast<float*>(smem + OFF_REDM);
    float* reds  = reinterpret_cast<float*>(smem + OFF_REDS);

    const int tid = threadIdx.x;
    const int l   = tid & 31;
    const int w   = tid >> 5;
    const int wm  = w & 3;
    const int wn  = w >> 2;
    const int p0  = blockIdx.x * 128;

    const float ls     = lsg[0];
    const float alpha2 = -0.5f * __expf(-2.0f * ls) * 1.4426950408889634f;  // alpha/ln2
    const float beta2  = -2.0f * alpha2;

    // prologue: X tile (hi|lo) + Y tile 0
#pragma unroll
    for (int it = 0; it < 8; ++it) {
        int u = tid + it * 512;
        int r = u >> 5, c = u & 31;
        const void* src = (c < 16) ? (const void*)(Xhi + (size_t)(p0 + r) * CDIM + c * 8)
                                   : (const void*)(Xlo + (size_t)(p0 + r) * CDIM + (c - 16) * 8);
        cpasync16(base + OFF_X + r * 512 + swzc(c, r), src);
    }
#pragma unroll
    for (int it = 0; it < 4; ++it) {
        int u = tid + it * 512;
        int r = u >> 4, c = u & 15;
        cpasync16(base + OFF_Y(0) + r * 256 + swzc(c, r), Yhi + (size_t)r * CDIM + c * 8);
    }
    cpcommit();
    if (tid < 128) ysq_s[tid] = alpha2 * Ysq[tid];

    float base2[4];
#pragma unroll
    for (int mf = 0; mf < 2; ++mf)
#pragma unroll
        for (int h = 0; h < 2; ++h)
            base2[mf * 2 + h] = alpha2 * Xsq[p0 + wm * 32 + mf * 16 + (l >> 2) + 8 * h];

    float mS[4], sS[4];
#pragma unroll
    for (int i = 0; i < 4; ++i) { mS[i] = -1e30f; sS[i] = 0.0f; }

    const int rx  = l & 7;
    const int aco = l >> 4;
    const int bco = (l >> 3) & 1;
    uint32_t arow[2], brow[2];
#pragma unroll
    for (int mf = 0; mf < 2; ++mf)
        arow[mf] = (uint32_t)((wm * 32 + mf * 16 + (l & 15)) * 512);
#pragma unroll
    for (int g2 = 0; g2 < 2; ++g2)
        brow[g2] = (uint32_t)((wn * 32 + g2 * 16 + (l & 7) + ((l >> 4) << 3)) * 256);

    for (int t = 0; t < QTILES; ++t) {
        const int cur = t & 1;
        if (t + 1 < QTILES) {
            const size_t q1 = (size_t)(t + 1) * 128;
#pragma unroll
            for (int it = 0; it < 4; ++it) {
                int u = tid + it * 512;
                int r = u >> 4, c = u & 15;
                cpasync16(base + OFF_Y(cur ^ 1) + r * 256 + swzc(c, r),
                          Yhi + (q1 + r) * CDIM + c * 8);
            }
            cpcommit();
            if (tid < 128) ysq_s[(cur ^ 1) * 128 + tid] = alpha2 * Ysq[q1 + tid];
            cpwait<1>();
        } else {
            cpwait<0>();
        }
        __syncthreads();   // Y(t) resident; colsm(t-1) consumed

        float acc[2][4][4];
#pragma unroll
        for (int mf = 0; mf < 2; ++mf)
#pragma unroll
            for (int nf = 0; nf < 4; ++nf)
#pragma unroll
                for (int k = 0; k < 4; ++k) acc[mf][nf][k] = 0.0f;

        const uint32_t Ab = base + OFF_X;
        const uint32_t Bb = base + OFF_Y(cur);
#pragma unroll
        for (int ks = 0; ks < 8; ++ks) {
            uint32_t b[2][4];
            const uint32_t sb = swzc(ks * 2 + bco, rx);
#pragma unroll
            for (int g2 = 0; g2 < 2; ++g2) ldsm_x4(b[g2], Bb + brow[g2] + sb);
#pragma unroll
            for (int p = 0; p < 2; ++p) {
                uint32_t a[2][4];
                const uint32_t sa = swzc(p * 16 + ks * 2 + aco, rx);
#pragma unroll
                for (int mf = 0; mf < 2; ++mf) ldsm_x4(a[mf], Ab + arow[mf] + sa);
#pragma unroll
                for (int mf = 0; mf < 2; ++mf)
#pragma unroll
                    for (int g2 = 0; g2 < 2; ++g2) {
                        mma16816(acc[mf][2 * g2],     a[mf], &b[g2][0]);
                        mma16816(acc[mf][2 * g2 + 1], a[mf], &b[g2][2]);
                    }
            }
        }

        // ---- epilogue: warp-common scale g, then plain-add reductions ----
        const float* tc = ysq_s + cur * 128;
        float tcv[4][2];
#pragma unroll
        for (int nf = 0; nf < 4; ++nf)
#pragma unroll
            for (int j = 0; j < 2; ++j)
                tcv[nf][j] = tc[wn * 32 + nf * 8 + 2 * (l & 3) + j];

        float g = -1e30f;
#pragma unroll
        for (int mf = 0; mf < 2; ++mf)
#pragma unroll
            for (int nf = 0; nf < 4; ++nf)
#pragma unroll
                for (int k = 0; k < 4; ++k) {
                    const int ri = mf * 2 + (k >> 1);
                    float v = fminf(base2[ri] + fmaf(acc[mf][nf][k], beta2, tcv[nf][k & 1]), 0.0f);
                    acc[mf][nf][k] = v;
                    g = fmaxf(g, v);
                }
#pragma unroll
        for (int off = 16; off; off >>= 1)
            g = fmaxf(g, __shfl_xor_sync(0xffffffffu, g, off));
#pragma unroll
        for (int mf = 0; mf < 2; ++mf)
#pragma unroll
            for (int nf = 0; nf < 4; ++nf)
#pragma unroll
                for (int k = 0; k < 4; ++k)
                    acc[mf][nf][k] = ex2f(acc[mf][nf][k] - g);

        // row sums (common g): quad shfl-adds, then one merge into running state
#pragma unroll
        for (int ri = 0; ri < 4; ++ri) {
            const int mf = ri >> 1, h = ri & 1;
            float P = 0.0f;
#pragma unroll
            for (int nf = 0; nf < 4; ++nf) P += acc[mf][nf][2 * h] + acc[mf][nf][2 * h + 1];
            P += __shfl_xor_sync(0xffffffffu, P, 1);
            P += __shfl_xor_sync(0xffffffffu, P, 2);
            merge_ms(mS[ri], sS[ri], g, P);
        }
        // col sums (common g): plain shfl-adds across the 8 row-lane groups
        float Q[8];
#pragma unroll
        for (int nf = 0; nf < 4; ++nf)
#pragma unroll
            for (int j = 0; j < 2; ++j)
                Q[nf * 2 + j] = acc[0][nf][j] + acc[0][nf][2 + j]
                              + acc[1][nf][j] + acc[1][nf][2 + j];
#pragma unroll
        for (int off = 4; off <= 16; off <<= 1)
#pragma unroll
            for (int i = 0; i < 8; ++i) Q[i] += __shfl_xor_sync(0xffffffffu, Q[i], off);
        if (l < 4) {
#pragma unroll
            for (int nf = 0; nf < 4; ++nf)
#pragma unroll
                for (int j = 0; j < 2; ++j) {
                    int c = wn * 32 + nf * 8 + 2 * l + j;
                    colsm[(wm * 128 + c) * 2 + 0] = g;
                    colsm[(wm * 128 + c) * 2 + 1] = Q[nf * 2 + j];
                }
        }
        __syncthreads();
        if (tid < 128) {
            float m = colsm[tid * 2], s = colsm[tid * 2 + 1];
#pragma unroll
            for (int gq = 1; gq < 4; ++gq)
                merge_ms(m, s, colsm[(gq * 128 + tid) * 2], colsm[(gq * 128 + tid) * 2 + 1]);
            cpm[(size_t)blockIdx.x * MCODE + t * 128 + tid] = m;
            cps[(size_t)blockIdx.x * MCODE + t * 128 + tid] = s;
        }
    }

    // row finalization: states already quad-uniform; merge across wn warps via smem
    __syncthreads();
    if ((l & 3) == 0) {
#pragma unroll
        for (int mf = 0; mf < 2; ++mf)
#pragma unroll
            for (int h = 0; h < 2; ++h) {
                int rloc = wm * 32 + mf * 16 + (l >> 2) + 8 * h;
                redm[wn * 128 + rloc] = mS[mf * 2 + h];
                reds[wn * 128 + rloc] = sS[mf * 2 + h];
            }
    }
    __syncthreads();
    if (tid < 128) {
        float m = redm[tid], s = reds[tid];
#pragma unroll
        for (int gq = 1; gq < 4; ++gq) merge_ms(m, s, redm[gq * 128 + tid], reds[gq * 128 + tid]);
        rowm[p0 + tid] = m;
        rows[p0 + tid] = s;
    }
}

// ---------------- merge column partials: parallel over p ----------------
// 128 blocks x 256 threads: 64 q per block, 4 p-chunks of 32 per q.
__global__ void colmerge(const float* __restrict__ cpm, const float* __restrict__ cps,
                         float* __restrict__ cm, float* __restrict__ cs) {
    __shared__ float sm_[4][64], ss_[4][64];
    const int qi = threadIdx.x & 63;
    const int pg = threadIdx.x >> 6;
    const int q  = blockIdx.x * 64 + qi;
    float m = -1e30f, s = 0.0f;
#pragma unroll 4
    for (int p = pg * 32; p < pg * 32 + 32; ++p)
        merge_ms(m, s, __ldg(cpm + (size_t)p * MCODE + q), __ldg(cps + (size_t)p * MCODE + q));
    sm_[pg][qi] = m; ss_[pg][qi] = s;
    __syncthreads();
    if (pg == 0) {
#pragma unroll
        for (int g = 1; g < 4; ++g) merge_ms(m, s, sm_[g][qi], ss_[g][qi]);
        cm[q] = m;
        cs[q] = s;
    }
}

// ---------------- finalize: mean of LSEs + constants ----------------
__global__ void finalize(const float* __restrict__ lsg, float* __restrict__ out) {
    __shared__ double red[256];
    const int which = blockIdx.x;
    const int P     = (which == 0) ? NTOK : MCODE;
    const float* pm = (which == 0) ? g_rm : g_cm;
    const float* ps = (which == 0) ? g_rs : g_cs;
    double acc = 0.0;
    for (int i = threadIdx.x; i < P; i += 256)
        acc += 0.6931471805599453 * ((double)pm[i] + (double)__log2f(ps[i]));
    red[threadIdx.x] = acc;
    __syncthreads();
    for (int st = 128; st; st >>= 1) {
        if (threadIdx.x < st) red[threadIdx.x] += red[threadIdx.x + st];
        __syncthreads();
    }
    if (threadIdx.x == 0) {
        float ls  = lsg[0];
        float cst = 0.5f * (float)CDIM * (2.0f * ls - 1.0f);
        float lg  = (which == 0) ? logf((float)MCODE) : logf((float)NTOK);
        out[which] = (float)(-(red[0] / (double)P)) + cst + lg;
    }
}

// ---------------- launch ----------------
extern "C" void kernel_launch(void* const* d_in, const int* in_sizes, int n_in,
                              void* d_out, int out_size) {
    (void)in_sizes; (void)n_in; (void)out_size;
    const float* z   = (const float*)d_in[0];
    const float* e   = (const float*)d_in[1];
    const float* lsg = (const float*)d_in[2];
    float* out = (float*)d_out;

    float *zsq, *esq, *rm, *rs, *cpm, *cps, *cm, *cs;
    __nv_bfloat16 *zhi, *zlo, *ehi;
    cudaGetSymbolAddress((void**)&zhi, g_zhi);
    cudaGetSymbolAddress((void**)&zlo, g_zlo);
    cudaGetSymbolAddress((void**)&ehi, g_ehi);
    cudaGetSymbolAddress((void**)&zsq, g_zsq);
    cudaGetSymbolAddress((void**)&esq, g_esq);
    cudaGetSymbolAddress((void**)&rm,  g_rm);
    cudaGetSymbolAddress((void**)&rs,  g_rs);
    cudaGetSymbolAddress((void**)&cpm, g_cpm);
    cudaGetSymbolAddress((void**)&cps, g_cps);
    cudaGetSymbolAddress((void**)&cm,  g_cm);
    cudaGetSymbolAddress((void**)&cs,  g_cs);

    cudaFuncSetAttribute(lse_single, cudaFuncAttributeMaxDynamicSharedMemorySize, SMEM_BYTES);

    fuse_z<<<512, 256>>>(z, zhi, zlo, zsq);
    fuse_e<<<MCODE / 8, 256>>>(e, ehi, esq);

    lse_single<<<PTILES, 512, SMEM_BYTES>>>(zhi, zlo, zsq, ehi, esq, lsg,
                                            rm, rs, cpm, cps);

    colmerge<<<MCODE / 64, 256>>>(cpm, cps, cm, cs);
    finalize<<<2, 256>>>(lsg, out);
}